// round 5
// baseline (speedup 1.0000x reference)
#include <cuda_runtime.h>
#include <cuda_fp16.h>

#define N_NODES 100000
#define N_EDGES 3200000
#define N_OCTS  (N_EDGES / 8)   // 8 edges per thread

// ---------------- scratch (device globals; no allocation allowed) ----------
__device__ float   g_deg[N_NODES];
__device__ float   g_dinv[N_NODES];
__device__ __half2 g_y[N_NODES];     // f16x2(dinv[n] * x[n])   layer-1 source msgs
__device__ float2  g_agg1[N_NODES];  // (A+I) @ y               f32 accumulation
__device__ __half2 g_zs[N_NODES];    // f16x2(dinv[n] * z[n])   layer-2 source msgs

// Vector f32x2 reduction to global (PTX 8.1+, sm_90+). Halves atomic op count.
__device__ __forceinline__ void red_add_v2(float2* addr, float a, float b) {
    asm volatile("red.global.add.v2.f32 [%0], {%1, %2};"
                 :: "l"(addr), "f"(a), "f"(b) : "memory");
}

// K1: degree init (self-loop contributes 1).
__global__ void k_init() {
    int n = blockIdx.x * blockDim.x + threadIdx.x;
    if (n < N_NODES) g_deg[n] = 1.0f;
}

// K2: degree accumulation at destinations. 8 edges/thread via 2x int4.
__global__ void k_degree(const int4* __restrict__ dst4) {
    int i = blockIdx.x * blockDim.x + threadIdx.x;
    if (i < N_OCTS) {
        int4 da = dst4[2 * i];
        int4 db = dst4[2 * i + 1];
        atomicAdd(&g_deg[da.x], 1.0f);
        atomicAdd(&g_deg[da.y], 1.0f);
        atomicAdd(&g_deg[da.z], 1.0f);
        atomicAdd(&g_deg[da.w], 1.0f);
        atomicAdd(&g_deg[db.x], 1.0f);
        atomicAdd(&g_deg[db.y], 1.0f);
        atomicAdd(&g_deg[db.z], 1.0f);
        atomicAdd(&g_deg[db.w], 1.0f);
    }
}

// K3: dinv = rsqrt(deg); y = dinv*x stored f16x2; agg1 init with f32 self-loop.
__global__ void k_prescale(const float* __restrict__ x) {
    int n = blockIdx.x * blockDim.x + threadIdx.x;
    if (n < N_NODES) {
        float di = rsqrtf(g_deg[n]);
        g_dinv[n] = di;
        float2 xv = reinterpret_cast<const float2*>(x)[n];
        float2 y  = make_float2(di * xv.x, di * xv.y);
        g_y[n]    = __floats2half2_rn(y.x, y.y);
        g_agg1[n] = y;                       // self-loop in full precision
    }
}

// K4: layer-1 aggregation: agg1[d] += y[s]. 8 edges/thread, gathers batched.
__global__ void k_agg1(const int4* __restrict__ src4,
                       const int4* __restrict__ dst4) {
    int i = blockIdx.x * blockDim.x + threadIdx.x;
    if (i < N_OCTS) {
        int4 sa = src4[2 * i];
        int4 sb = src4[2 * i + 1];
        int4 da = dst4[2 * i];
        int4 db = dst4[2 * i + 1];
        __half2 m0 = g_y[sa.x];
        __half2 m1 = g_y[sa.y];
        __half2 m2 = g_y[sa.z];
        __half2 m3 = g_y[sa.w];
        __half2 m4 = g_y[sb.x];
        __half2 m5 = g_y[sb.y];
        __half2 m6 = g_y[sb.z];
        __half2 m7 = g_y[sb.w];
        float2 y0 = __half22float2(m0);
        float2 y1 = __half22float2(m1);
        float2 y2 = __half22float2(m2);
        float2 y3 = __half22float2(m3);
        float2 y4 = __half22float2(m4);
        float2 y5 = __half22float2(m5);
        float2 y6 = __half22float2(m6);
        float2 y7 = __half22float2(m7);
        red_add_v2(&g_agg1[da.x], y0.x, y0.y);
        red_add_v2(&g_agg1[da.y], y1.x, y1.y);
        red_add_v2(&g_agg1[da.z], y2.x, y2.y);
        red_add_v2(&g_agg1[da.w], y3.x, y3.y);
        red_add_v2(&g_agg1[db.x], y4.x, y4.y);
        red_add_v2(&g_agg1[db.y], y5.x, y5.y);
        red_add_v2(&g_agg1[db.z], y6.x, y6.y);
        red_add_v2(&g_agg1[db.w], y7.x, y7.y);
    }
}

// K5: per-node fused dense chain.
//   a  = dinv[n] * agg1[n]              (destination post-scale, layer 1)
//   h  = relu(a @ W1^T + b1)            (64-dim, registers only)
//   z  = h @ W2^T                       (2-dim)
//   zs = dinv[n] * z                    (source pre-scale, layer 2)
//   out[n] = zs (f32)                   (self-loop init of layer-2 aggregation)
__global__ void k_node(const float* __restrict__ W1,
                       const float* __restrict__ b1,
                       const float* __restrict__ W2,
                       float2* __restrict__ out) {
    __shared__ float sW1[128];   // W1 row-major [64,2]
    __shared__ float sb1[64];
    __shared__ float sW2[128];   // W2 row-major [2,64]
    int t = threadIdx.x;
    if (t < 128)              sW1[t]       = W1[t];
    if (t < 64)               sb1[t]       = b1[t];
    if (t >= 128 && t < 256)  sW2[t - 128] = W2[t - 128];
    __syncthreads();

    int n = blockIdx.x * blockDim.x + t;
    if (n >= N_NODES) return;

    float  di = g_dinv[n];
    float2 ag = g_agg1[n];
    float  ax = di * ag.x, ay = di * ag.y;

    float zx = 0.0f, zy = 0.0f;
#pragma unroll
    for (int j = 0; j < 64; j++) {
        float h = fmaf(sW1[2 * j], ax, fmaf(sW1[2 * j + 1], ay, sb1[j]));
        h = fmaxf(h, 0.0f);
        zx = fmaf(sW2[j],      h, zx);
        zy = fmaf(sW2[64 + j], h, zy);
    }
    float zsx = di * zx, zsy = di * zy;
    g_zs[n] = __floats2half2_rn(zsx, zsy);
    out[n]  = make_float2(zsx, zsy);         // self-loop in full precision
}

// K6: layer-2 aggregation directly into d_out: out[d] += zs[s].
__global__ void k_agg2(const int4* __restrict__ src4,
                       const int4* __restrict__ dst4,
                       float2* __restrict__ out) {
    int i = blockIdx.x * blockDim.x + threadIdx.x;
    if (i < N_OCTS) {
        int4 sa = src4[2 * i];
        int4 sb = src4[2 * i + 1];
        int4 da = dst4[2 * i];
        int4 db = dst4[2 * i + 1];
        __half2 m0 = g_zs[sa.x];
        __half2 m1 = g_zs[sa.y];
        __half2 m2 = g_zs[sa.z];
        __half2 m3 = g_zs[sa.w];
        __half2 m4 = g_zs[sb.x];
        __half2 m5 = g_zs[sb.y];
        __half2 m6 = g_zs[sb.z];
        __half2 m7 = g_zs[sb.w];
        float2 z0 = __half22float2(m0);
        float2 z1 = __half22float2(m1);
        float2 z2 = __half22float2(m2);
        float2 z3 = __half22float2(m3);
        float2 z4 = __half22float2(m4);
        float2 z5 = __half22float2(m5);
        float2 z6 = __half22float2(m6);
        float2 z7 = __half22float2(m7);
        red_add_v2(&out[da.x], z0.x, z0.y);
        red_add_v2(&out[da.y], z1.x, z1.y);
        red_add_v2(&out[da.z], z2.x, z2.y);
        red_add_v2(&out[da.w], z3.x, z3.y);
        red_add_v2(&out[db.x], z4.x, z4.y);
        red_add_v2(&out[db.y], z5.x, z5.y);
        red_add_v2(&out[db.z], z6.x, z6.y);
        red_add_v2(&out[db.w], z7.x, z7.y);
    }
}

// K7: destination post-scale + bias: out[n] = dinv[n]*out[n] + b2.
__global__ void k_final(const float* __restrict__ b2,
                        float2* __restrict__ out) {
    int n = blockIdx.x * blockDim.x + threadIdx.x;
    if (n < N_NODES) {
        float di = g_dinv[n];
        float2 o = out[n];
        float bb0 = __ldg(&b2[0]), bb1 = __ldg(&b2[1]);
        out[n] = make_float2(fmaf(di, o.x, bb0), fmaf(di, o.y, bb1));
    }
}

extern "C" void kernel_launch(void* const* d_in, const int* in_sizes, int n_in,
                              void* d_out, int out_size) {
    const float* x  = (const float*)d_in[0];
    const int*   ei = (const int*)d_in[1];
    const float* W1 = (const float*)d_in[2];
    const float* b1 = (const float*)d_in[3];
    const float* W2 = (const float*)d_in[4];
    const float* b2 = (const float*)d_in[5];
    float2*      out = (float2*)d_out;

    const int4* src4 = (const int4*)ei;
    const int4* dst4 = (const int4*)(ei + N_EDGES);

    const int TB = 256;
    int nb_nodes = (N_NODES + TB - 1) / TB;
    int nb_octs  = (N_OCTS + TB - 1) / TB;

    k_init    <<<nb_nodes, TB>>>();
    k_degree  <<<nb_octs,  TB>>>(dst4);
    k_prescale<<<nb_nodes, TB>>>(x);
    k_agg1    <<<nb_octs,  TB>>>(src4, dst4);
    k_node    <<<nb_nodes, TB>>>(W1, b1, W2, out);
    k_agg2    <<<nb_octs,  TB>>>(src4, dst4, out);
    k_final   <<<nb_nodes, TB>>>(b2, out);
}

// round 6
// speedup vs baseline: 1.0459x; 1.0459x over previous
#include <cuda_runtime.h>
#include <cuda_fp16.h>

#define N_NODES 100000
#define N_EDGES 3200000
#define N_QUADS (N_EDGES / 4)   // 4 edges per thread (best measured config)

// ---------------- scratch (device globals; no allocation allowed) ----------
__device__ float   g_deg[N_NODES];   // zeroed by cudaMemsetAsync; self-loop +1 folded into prescale
__device__ float   g_dinv[N_NODES];
__device__ __half2 g_y[N_NODES];     // f16x2(dinv[n] * x[n])   layer-1 source msgs
__device__ float2  g_agg1[N_NODES];  // (A+I) @ y               f32 accumulation
__device__ __half2 g_zs[N_NODES];    // f16x2(dinv[n] * z[n])   layer-2 source msgs

// Vector f32x2 reduction to global (PTX 8.1+, sm_90+). Halves atomic op count.
__device__ __forceinline__ void red_add_v2(float2* addr, float a, float b) {
    asm volatile("red.global.add.v2.f32 [%0], {%1, %2};"
                 :: "l"(addr), "f"(a), "f"(b) : "memory");
}

// K2: degree accumulation at destinations. 4 edges per thread via int4.
__global__ void k_degree(const int* __restrict__ dst) {
    int i = blockIdx.x * blockDim.x + threadIdx.x;
    if (i < N_QUADS) {
        int4 d = reinterpret_cast<const int4*>(dst)[i];
        atomicAdd(&g_deg[d.x], 1.0f);
        atomicAdd(&g_deg[d.y], 1.0f);
        atomicAdd(&g_deg[d.z], 1.0f);
        atomicAdd(&g_deg[d.w], 1.0f);
    }
}

// K3: dinv = rsqrt(deg+1); y = dinv*x stored f16x2; agg1 init with f32 self-loop.
__global__ void k_prescale(const float* __restrict__ x) {
    int n = blockIdx.x * blockDim.x + threadIdx.x;
    if (n < N_NODES) {
        float di = rsqrtf(g_deg[n] + 1.0f);   // +1 = self-loop
        g_dinv[n] = di;
        float2 xv = reinterpret_cast<const float2*>(x)[n];
        float2 y  = make_float2(di * xv.x, di * xv.y);
        g_y[n]    = __floats2half2_rn(y.x, y.y);
        g_agg1[n] = y;                        // self-loop in full precision
    }
}

// K4: layer-1 aggregation: agg1[d] += y[s].
__global__ void k_agg1(const int* __restrict__ src,
                       const int* __restrict__ dst) {
    int i = blockIdx.x * blockDim.x + threadIdx.x;
    if (i < N_QUADS) {
        int4 s = reinterpret_cast<const int4*>(src)[i];
        int4 d = reinterpret_cast<const int4*>(dst)[i];
        float2 y0 = __half22float2(g_y[s.x]);
        float2 y1 = __half22float2(g_y[s.y]);
        float2 y2 = __half22float2(g_y[s.z]);
        float2 y3 = __half22float2(g_y[s.w]);
        red_add_v2(&g_agg1[d.x], y0.x, y0.y);
        red_add_v2(&g_agg1[d.y], y1.x, y1.y);
        red_add_v2(&g_agg1[d.z], y2.x, y2.y);
        red_add_v2(&g_agg1[d.w], y3.x, y3.y);
    }
}

// K5: per-node fused dense chain.
//   a  = dinv[n] * agg1[n]              (destination post-scale, layer 1)
//   h  = relu(a @ W1^T + b1)            (64-dim, registers only)
//   z  = h @ W2^T                       (2-dim)
//   zs = dinv[n] * z                    (source pre-scale, layer 2)
//   out[n] = zs (f32)                   (self-loop init of layer-2 aggregation)
__global__ void k_node(const float* __restrict__ W1,
                       const float* __restrict__ b1,
                       const float* __restrict__ W2,
                       float2* __restrict__ out) {
    __shared__ float sW1[128];   // W1 row-major [64,2]
    __shared__ float sb1[64];
    __shared__ float sW2[128];   // W2 row-major [2,64]
    int t = threadIdx.x;
    if (t < 128)              sW1[t]       = W1[t];
    if (t < 64)               sb1[t]       = b1[t];
    if (t >= 128 && t < 256)  sW2[t - 128] = W2[t - 128];
    __syncthreads();

    int n = blockIdx.x * blockDim.x + t;
    if (n >= N_NODES) return;

    float  di = g_dinv[n];
    float2 ag = g_agg1[n];
    float  ax = di * ag.x, ay = di * ag.y;

    float zx = 0.0f, zy = 0.0f;
#pragma unroll
    for (int j = 0; j < 64; j++) {
        float h = fmaf(sW1[2 * j], ax, fmaf(sW1[2 * j + 1], ay, sb1[j]));
        h = fmaxf(h, 0.0f);
        zx = fmaf(sW2[j],      h, zx);
        zy = fmaf(sW2[64 + j], h, zy);
    }
    float zsx = di * zx, zsy = di * zy;
    g_zs[n] = __floats2half2_rn(zsx, zsy);
    out[n]  = make_float2(zsx, zsy);          // self-loop in full precision
}

// K6: layer-2 aggregation directly into d_out: out[d] += zs[s].
__global__ void k_agg2(const int* __restrict__ src,
                       const int* __restrict__ dst,
                       float2* __restrict__ out) {
    int i = blockIdx.x * blockDim.x + threadIdx.x;
    if (i < N_QUADS) {
        int4 s = reinterpret_cast<const int4*>(src)[i];
        int4 d = reinterpret_cast<const int4*>(dst)[i];
        float2 z0 = __half22float2(g_zs[s.x]);
        float2 z1 = __half22float2(g_zs[s.y]);
        float2 z2 = __half22float2(g_zs[s.z]);
        float2 z3 = __half22float2(g_zs[s.w]);
        red_add_v2(&out[d.x], z0.x, z0.y);
        red_add_v2(&out[d.y], z1.x, z1.y);
        red_add_v2(&out[d.z], z2.x, z2.y);
        red_add_v2(&out[d.w], z3.x, z3.y);
    }
}

// K7: destination post-scale + bias: out[n] = dinv[n]*out[n] + b2.
__global__ void k_final(const float* __restrict__ b2,
                        float2* __restrict__ out) {
    int n = blockIdx.x * blockDim.x + threadIdx.x;
    if (n < N_NODES) {
        float di = g_dinv[n];
        float2 o = out[n];
        float bb0 = __ldg(&b2[0]), bb1 = __ldg(&b2[1]);
        out[n] = make_float2(fmaf(di, o.x, bb0), fmaf(di, o.y, bb1));
    }
}

extern "C" void kernel_launch(void* const* d_in, const int* in_sizes, int n_in,
                              void* d_out, int out_size) {
    const float* x  = (const float*)d_in[0];
    const int*   ei = (const int*)d_in[1];
    const float* W1 = (const float*)d_in[2];
    const float* b1 = (const float*)d_in[3];
    const float* W2 = (const float*)d_in[4];
    const float* b2 = (const float*)d_in[5];
    float2*      out = (float2*)d_out;

    const int* src = ei;
    const int* dst = ei + N_EDGES;

    const int TB = 256;
    int nb_nodes = (N_NODES + TB - 1) / TB;
    int nb_quads = (N_QUADS + TB - 1) / TB;

    // Zero degree buffer (capturable; not an allocation). Self-loop +1 folded
    // into k_prescale.
    void* deg_ptr = nullptr;
    cudaGetSymbolAddress(&deg_ptr, g_deg);
    cudaMemsetAsync(deg_ptr, 0, N_NODES * sizeof(float));

    k_degree  <<<nb_quads, TB>>>(dst);
    k_prescale<<<nb_nodes, TB>>>(x);
    k_agg1    <<<nb_quads, TB>>>(src, dst);
    k_node    <<<nb_nodes, TB>>>(W1, b1, W2, out);
    k_agg2    <<<nb_quads, TB>>>(src, dst, out);
    k_final   <<<nb_nodes, TB>>>(b2, out);
}

// round 7
// speedup vs baseline: 1.0705x; 1.0235x over previous
#include <cuda_runtime.h>
#include <cuda_fp16.h>

#define N_NODES 100000
#define N_EDGES 3200000
#define N_QUADS (N_EDGES / 4)   // 4 edges per thread (best measured config)

// ---------------- scratch (device globals; no allocation allowed) ----------
__device__ float   g_deg[N_NODES];   // zeroed by cudaMemsetAsync; self-loop +1 folded into prescale
__device__ float   g_dinv[N_NODES];
__device__ __half2 g_y[N_NODES];     // f16x2(dinv[n] * x[n])   layer-1 source msgs
__device__ float2  g_agg1[N_NODES];  // (A+I) @ y               f32 accumulation
__device__ __half2 g_zs[N_NODES];    // f16x2(dinv[n] * z[n])   layer-2 source msgs

// Vector f32x2 reduction to global (PTX 8.1+, sm_90+). Halves atomic op count.
__device__ __forceinline__ void red_add_v2(float2* addr, float a, float b) {
    asm volatile("red.global.add.v2.f32 [%0], {%1, %2};"
                 :: "l"(addr), "f"(a), "f"(b) : "memory");
}

// K2: degree accumulation at destinations. 4 edges per thread via int4.
__global__ void k_degree(const int* __restrict__ dst) {
    int i = blockIdx.x * blockDim.x + threadIdx.x;
    if (i < N_QUADS) {
        int4 d = reinterpret_cast<const int4*>(dst)[i];
        atomicAdd(&g_deg[d.x], 1.0f);
        atomicAdd(&g_deg[d.y], 1.0f);
        atomicAdd(&g_deg[d.z], 1.0f);
        atomicAdd(&g_deg[d.w], 1.0f);
    }
}

// K3: dinv = rsqrt(deg+1); y = dinv*x stored f16x2; agg1 init with f32 self-loop.
__global__ void k_prescale(const float* __restrict__ x) {
    int n = blockIdx.x * blockDim.x + threadIdx.x;
    if (n < N_NODES) {
        float di = rsqrtf(g_deg[n] + 1.0f);   // +1 = self-loop
        g_dinv[n] = di;
        float2 xv = reinterpret_cast<const float2*>(x)[n];
        float2 y  = make_float2(di * xv.x, di * xv.y);
        g_y[n]    = __floats2half2_rn(y.x, y.y);
        g_agg1[n] = y;                        // self-loop in full precision
    }
}

// K4: layer-1 aggregation: agg1[d] += y[s].
__global__ void k_agg1(const int* __restrict__ src,
                       const int* __restrict__ dst) {
    int i = blockIdx.x * blockDim.x + threadIdx.x;
    if (i < N_QUADS) {
        int4 s = reinterpret_cast<const int4*>(src)[i];
        int4 d = reinterpret_cast<const int4*>(dst)[i];
        float2 y0 = __half22float2(g_y[s.x]);
        float2 y1 = __half22float2(g_y[s.y]);
        float2 y2 = __half22float2(g_y[s.z]);
        float2 y3 = __half22float2(g_y[s.w]);
        red_add_v2(&g_agg1[d.x], y0.x, y0.y);
        red_add_v2(&g_agg1[d.y], y1.x, y1.y);
        red_add_v2(&g_agg1[d.z], y2.x, y2.y);
        red_add_v2(&g_agg1[d.w], y3.x, y3.y);
    }
}

// K5: per-node fused dense chain, weights packed as float4 to cut LDS issue 2.5x.
//   sWp[j] = {W1[j][0], W1[j][1], W2[0][j], W2[1][j]}
//   a  = dinv[n] * agg1[n]
//   h  = relu(a . W1[j] + b1[j]);  z += h * W2[:,j]
//   zs = dinv[n] * z;  out[n] = zs (self-loop init of layer-2 aggregation)
__global__ void k_node(const float* __restrict__ W1,
                       const float* __restrict__ b1,
                       const float* __restrict__ W2,
                       float2* __restrict__ out) {
    __shared__ float4 sWp[64];
    __shared__ float  sb1[64];
    int t = threadIdx.x;
    if (t < 64) {
        sWp[t] = make_float4(W1[2 * t], W1[2 * t + 1], W2[t], W2[64 + t]);
        sb1[t] = b1[t];
    }
    __syncthreads();

    int n = blockIdx.x * blockDim.x + t;
    if (n >= N_NODES) return;

    float  di = g_dinv[n];
    float2 ag = g_agg1[n];
    float  ax = di * ag.x, ay = di * ag.y;

    float zx = 0.0f, zy = 0.0f;
#pragma unroll
    for (int j = 0; j < 64; j++) {
        float4 w = sWp[j];
        float h = fmaf(w.x, ax, fmaf(w.y, ay, sb1[j]));
        h = fmaxf(h, 0.0f);
        zx = fmaf(w.z, h, zx);
        zy = fmaf(w.w, h, zy);
    }
    float zsx = di * zx, zsy = di * zy;
    g_zs[n] = __floats2half2_rn(zsx, zsy);
    out[n]  = make_float2(zsx, zsy);          // self-loop in full precision
}

// K6: layer-2 aggregation directly into d_out: out[d] += zs[s].
__global__ void k_agg2(const int* __restrict__ src,
                       const int* __restrict__ dst,
                       float2* __restrict__ out) {
    int i = blockIdx.x * blockDim.x + threadIdx.x;
    if (i < N_QUADS) {
        int4 s = reinterpret_cast<const int4*>(src)[i];
        int4 d = reinterpret_cast<const int4*>(dst)[i];
        float2 z0 = __half22float2(g_zs[s.x]);
        float2 z1 = __half22float2(g_zs[s.y]);
        float2 z2 = __half22float2(g_zs[s.z]);
        float2 z3 = __half22float2(g_zs[s.w]);
        red_add_v2(&out[d.x], z0.x, z0.y);
        red_add_v2(&out[d.y], z1.x, z1.y);
        red_add_v2(&out[d.z], z2.x, z2.y);
        red_add_v2(&out[d.w], z3.x, z3.y);
    }
}

// K7: destination post-scale + bias: out[n] = dinv[n]*out[n] + b2.
__global__ void k_final(const float* __restrict__ b2,
                        float2* __restrict__ out) {
    int n = blockIdx.x * blockDim.x + threadIdx.x;
    if (n < N_NODES) {
        float di = g_dinv[n];
        float2 o = out[n];
        float bb0 = __ldg(&b2[0]), bb1 = __ldg(&b2[1]);
        out[n] = make_float2(fmaf(di, o.x, bb0), fmaf(di, o.y, bb1));
    }
}

extern "C" void kernel_launch(void* const* d_in, const int* in_sizes, int n_in,
                              void* d_out, int out_size) {
    const float* x  = (const float*)d_in[0];
    const int*   ei = (const int*)d_in[1];
    const float* W1 = (const float*)d_in[2];
    const float* b1 = (const float*)d_in[3];
    const float* W2 = (const float*)d_in[4];
    const float* b2 = (const float*)d_in[5];
    float2*      out = (float2*)d_out;

    const int* src = ei;
    const int* dst = ei + N_EDGES;

    const int TB = 256;
    int nb_nodes = (N_NODES + TB - 1) / TB;
    int nb_quads = (N_QUADS + TB - 1) / TB;

    // Zero degree buffer (capturable; not an allocation). Self-loop +1 folded
    // into k_prescale.
    void* deg_ptr = nullptr;
    cudaGetSymbolAddress(&deg_ptr, g_deg);
    cudaMemsetAsync(deg_ptr, 0, N_NODES * sizeof(float));

    k_degree  <<<nb_quads, TB>>>(dst);
    k_prescale<<<nb_nodes, TB>>>(x);
    k_agg1    <<<nb_quads, TB>>>(src, dst);
    k_node    <<<nb_nodes, TB>>>(W1, b1, W2, out);
    k_agg2    <<<nb_quads, TB>>>(src, dst, out);
    k_final   <<<nb_nodes, TB>>>(b2, out);
}